// round 5
// baseline (speedup 1.0000x reference)
#include <cuda_runtime.h>
#include <cstdint>

#define HID 128
#define MAXN 50000
#define MAXE 640000

// ---------------- scratch (device globals; no allocation allowed) ----------------
__device__ __align__(256) float g_z[MAXN * HID];       // raw (pre-BN) layer output
__device__ __align__(256) float g_t[MAXN * HID];       // post-GEMM1 pre-BN
__device__ __align__(256) float g_stats[8 * 2 * HID];  // per-layer [sum|sumsq] slots
__device__ int g_cnt[MAXN];
__device__ int g_rowptr[MAXN + 1];
__device__ int g_elist[MAXE];

// ---------------- f32x2 helpers ----------------
__device__ __forceinline__ unsigned long long pk2(float a) {
    unsigned long long r;
    asm("mov.b64 %0, {%1, %1};" : "=l"(r) : "f"(a));
    return r;
}
__device__ __forceinline__ void fma2(unsigned long long& d, unsigned long long a, unsigned long long b) {
    asm("fma.rn.f32x2 %0, %1, %2, %0;" : "+l"(d) : "l"(a), "l"(b));
}
__device__ __forceinline__ float2 upk(unsigned long long v) {
    float2 r;
    asm("mov.b64 {%0, %1}, %2;" : "=f"(r.x), "=f"(r.y) : "l"(v));
    return r;
}

// ================= CSR build =================
__global__ void hist_kernel(const int* __restrict__ dst, int E) {
    int i = blockIdx.x * blockDim.x + threadIdx.x;
    if (i < E) atomicAdd(&g_cnt[dst[i]], 1);
}

__global__ void __launch_bounds__(1024) scan_kernel(int N, int E) {
    __shared__ int part[1024];
    int tid = threadIdx.x;
    int chunk = (N + 1023) / 1024;
    int base = tid * chunk;
    int s = 0;
    for (int j = 0; j < chunk; j++) {
        int idx = base + j;
        if (idx < N) s += g_cnt[idx];
    }
    part[tid] = s;
    __syncthreads();
    for (int off = 1; off < 1024; off <<= 1) {
        int v = (tid >= off) ? part[tid - off] : 0;
        __syncthreads();
        part[tid] += v;
        __syncthreads();
    }
    int run = (tid == 0) ? 0 : part[tid - 1];
    for (int j = 0; j < chunk; j++) {
        int idx = base + j;
        if (idx < N) {
            g_rowptr[idx] = run;
            run += g_cnt[idx];
            g_cnt[idx] = 0;
        }
    }
    if (tid == 1023) g_rowptr[N] = E;
}

__global__ void scatter_kernel(const int* __restrict__ dst, int E) {
    int i = blockIdx.x * blockDim.x + threadIdx.x;
    if (i < E) {
        int d = dst[i];
        int p = atomicAdd(&g_cnt[d], 1);
        g_elist[g_rowptr[d] + p] = i;
    }
}

// ================= fused kernels =================
// Persistent GEMM, BM=64, 256 threads. Warp w: rows w*8+rs*4..+3 (rs=lane>>4),
// cols (lane&15)*8. W LDS conflict-free, A LDS broadcast.
static const int GEMM_SMEM = (HID * HID + 64 * 132 + 2 * HID) * 4;  // 100352 B

// ---- shared device routine: mainloop + epilogue (RELU_OUT) + optional stats ----
template <bool RELU_OUT, bool STATS>
__device__ __forceinline__ void gemm_tile_body(
    float* __restrict__ Ws, float* __restrict__ As,
    const float* __restrict__ bias, float* __restrict__ out,
    float* __restrict__ stat_out, int row0, int M,
    int lane, int wid) {
    const int rs = lane >> 4;          // 0/1
    const int cx = (lane & 15) * 8;    // col base
    const int arow = wid * 8 + rs * 4;

    unsigned long long acc[16];
#pragma unroll
    for (int i = 0; i < 16; i++) acc[i] = 0ull;

#pragma unroll 2
    for (int kk = 0; kk < HID; kk += 4) {
        float ar[4][4];
#pragma unroll
        for (int r = 0; r < 4; r++)
            *(float4*)ar[r] = *(const float4*)&As[(arow + r) * 132 + kk];
#pragma unroll
        for (int j = 0; j < 4; j++) {
            ulonglong2 wA = *(const ulonglong2*)&Ws[(kk + j) * HID + cx];
            ulonglong2 wB = *(const ulonglong2*)&Ws[(kk + j) * HID + cx + 4];
#pragma unroll
            for (int r = 0; r < 4; r++) {
                unsigned long long pa = pk2(ar[r][j]);
                fma2(acc[r * 4 + 0], pa, wA.x);
                fma2(acc[r * 4 + 1], pa, wA.y);
                fma2(acc[r * 4 + 2], pa, wB.x);
                fma2(acc[r * 4 + 3], pa, wB.y);
            }
        }
    }

    float bb[8];
    *(float4*)&bb[0] = __ldg((const float4*)(bias + cx));
    *(float4*)&bb[4] = __ldg((const float4*)(bias + cx + 4));
    float csum[8], csq[8];
#pragma unroll
    for (int j = 0; j < 8; j++) { csum[j] = 0.f; csq[j] = 0.f; }

#pragma unroll
    for (int r = 0; r < 4; r++) {
        int gr = row0 + arow + r;
        if (gr < M) {
            float v[8];
#pragma unroll
            for (int p = 0; p < 4; p++) {
                float2 u = upk(acc[r * 4 + p]);
                v[2 * p] = u.x + bb[2 * p];
                v[2 * p + 1] = u.y + bb[2 * p + 1];
            }
            if (RELU_OUT) {
#pragma unroll
                for (int j = 0; j < 8; j++) v[j] = fmaxf(v[j], 0.f);
            }
            *(float4*)(out + (size_t)gr * HID + cx) = make_float4(v[0], v[1], v[2], v[3]);
            *(float4*)(out + (size_t)gr * HID + cx + 4) = make_float4(v[4], v[5], v[6], v[7]);
            if (STATS) {
#pragma unroll
                for (int j = 0; j < 8; j++) { csum[j] += v[j]; csq[j] += v[j] * v[j]; }
            }
        }
    }

    if (STATS) {
        // red[cid][0..127]=sum, [128..255]=sq ; cid = wid*2+rs (16 groups) -> 16KB in As
        float* red = As;
        int cid = wid * 2 + rs;
        __syncthreads();
#pragma unroll
        for (int j = 0; j < 4; j++) {
            *(float4*)&red[cid * 256 + cx] = make_float4(csum[0], csum[1], csum[2], csum[3]);
            *(float4*)&red[cid * 256 + cx + 4] = make_float4(csum[4], csum[5], csum[6], csum[7]);
            *(float4*)&red[cid * 256 + 128 + cx] = make_float4(csq[0], csq[1], csq[2], csq[3]);
            *(float4*)&red[cid * 256 + 128 + cx + 4] = make_float4(csq[4], csq[5], csq[6], csq[7]);
            break;  // single store set (loop kept for clarity)
        }
        __syncthreads();
#pragma unroll
        for (int s = 8; s > 0; s >>= 1) {
            for (int k = threadIdx.x; k < s * 256; k += 256) {
                int c = k >> 8, i = k & 255;
                red[c * 256 + i] += red[(c + s) * 256 + i];
            }
            __syncthreads();
        }
        if (threadIdx.x < 128) {
            atomicAdd(&stat_out[threadIdx.x], red[threadIdx.x]);
            atomicAdd(&stat_out[HID + threadIdx.x], red[128 + threadIdx.x]);
        }
        __syncthreads();  // before next tile reuses As
    } else {
        __syncthreads();
    }
}

// ---- K1: fused edge-aggregate + GEMM1 (+ BN-on-input via scale/shift) ----
template <bool BN_IN>
__global__ void __launch_bounds__(256) k1_kernel(
    const float* __restrict__ z, const float* __restrict__ ea,
    const int* __restrict__ srcI,
    const float* __restrict__ stat_in, const float* __restrict__ gamma,
    const float* __restrict__ beta, float invN,
    const float* __restrict__ W, const float* __restrict__ bias,
    float* __restrict__ out, float* __restrict__ stat_out,
    int M, int nTiles) {
    extern __shared__ float smem[];
    float* Ws = smem;
    float* As = smem + HID * HID;
    float* s_sc = smem + HID * HID + 64 * 132;
    float* s_sh = s_sc + HID;

    const int tid = threadIdx.x;
    const int lane = tid & 31;
    const int wid = tid >> 5;

    if (tid < HID) {
        if (BN_IN) {
            float mu = stat_in[tid] * invN;
            float var = stat_in[HID + tid] * invN - mu * mu;
            float sv = gamma[tid] * rsqrtf(var + 1e-5f);
            s_sc[tid] = sv;
            s_sh[tid] = beta[tid] - sv * mu;
        } else {
            s_sc[tid] = 1.f;
            s_sh[tid] = 0.f;
        }
    }
    // stage W once
    const float4* Wg = (const float4*)W;
    float4* Ws4 = (float4*)Ws;
#pragma unroll
    for (int i = 0; i < 16; i++) Ws4[tid + 256 * i] = __ldg(Wg + tid + 256 * i);
    __syncthreads();

    float4 sc = *(const float4*)&s_sc[lane * 4];
    float4 sh = *(const float4*)&s_sh[lane * 4];

    for (int tile = blockIdx.x; tile < nTiles; tile += gridDim.x) {
        int row0 = tile * 64;
        // ---- aggregate + stage: warp handles 8 nodes ----
#pragma unroll 1
        for (int j = 0; j < 8; j++) {
            int r = wid * 8 + j;
            int gr = row0 + r;
            float4 acc = make_float4(0.f, 0.f, 0.f, 0.f);
            if (gr < M) {
                int idx = __ldg(g_rowptr + gr);
                const int end = __ldg(g_rowptr + gr + 1);
#define EDGE_BODY(E_, S_)                                                         \
    {                                                                             \
        float4 zv = __ldg((const float4*)(z + (size_t)(S_) * HID) + lane);        \
        float4 av = __ldcs((const float4*)(ea + (size_t)(E_) * HID) + lane);      \
        if (BN_IN) {                                                              \
            zv.x = fmaf(sc.x, zv.x, sh.x); zv.y = fmaf(sc.y, zv.y, sh.y);         \
            zv.z = fmaf(sc.z, zv.z, sh.z); zv.w = fmaf(sc.w, zv.w, sh.w);         \
        }                                                                         \
        acc.x += fmaxf(zv.x + av.x, 0.f);                                         \
        acc.y += fmaxf(zv.y + av.y, 0.f);                                         \
        acc.z += fmaxf(zv.z + av.z, 0.f);                                         \
        acc.w += fmaxf(zv.w + av.w, 0.f);                                         \
    }
                for (; idx + 4 <= end; idx += 4) {
                    int e0 = __ldg(g_elist + idx);
                    int e1 = __ldg(g_elist + idx + 1);
                    int e2 = __ldg(g_elist + idx + 2);
                    int e3 = __ldg(g_elist + idx + 3);
                    int s0 = __ldg(srcI + e0);
                    int s1 = __ldg(srcI + e1);
                    int s2 = __ldg(srcI + e2);
                    int s3 = __ldg(srcI + e3);
                    EDGE_BODY(e0, s0) EDGE_BODY(e1, s1) EDGE_BODY(e2, s2) EDGE_BODY(e3, s3)
                }
                for (; idx < end; idx++) {
                    int e0 = __ldg(g_elist + idx);
                    int s0 = __ldg(srcI + e0);
                    EDGE_BODY(e0, s0)
                }
#undef EDGE_BODY
                // self term: BN(z[gr]) + acc
                float4 zv = __ldg((const float4*)(z + (size_t)gr * HID) + lane);
                if (BN_IN) {
                    zv.x = fmaf(sc.x, zv.x, sh.x); zv.y = fmaf(sc.y, zv.y, sh.y);
                    zv.z = fmaf(sc.z, zv.z, sh.z); zv.w = fmaf(sc.w, zv.w, sh.w);
                }
                acc.x += zv.x; acc.y += zv.y; acc.z += zv.z; acc.w += zv.w;
            }
            *(float4*)&As[r * 132 + lane * 4] = acc;
        }
        __syncthreads();
        gemm_tile_body<false, true>(Ws, As, bias, out, stat_out, row0, M, lane, wid);
    }
}

// ---- K2: GEMM2 with BN(stat_in)+ReLU on input, ReLU on output ----
template <bool STATS>
__global__ void __launch_bounds__(256) k2_kernel(
    const float* __restrict__ A,
    const float* __restrict__ stat_in, const float* __restrict__ gamma,
    const float* __restrict__ beta, float invN,
    const float* __restrict__ W, const float* __restrict__ bias,
    float* __restrict__ out, float* __restrict__ stat_out,
    int M, int nTiles) {
    extern __shared__ float smem[];
    float* Ws = smem;
    float* As = smem + HID * HID;
    float* s_sc = smem + HID * HID + 64 * 132;
    float* s_sh = s_sc + HID;

    const int tid = threadIdx.x;
    const int lane = tid & 31;
    const int wid = tid >> 5;

    if (tid < HID) {
        float mu = stat_in[tid] * invN;
        float var = stat_in[HID + tid] * invN - mu * mu;
        float sv = gamma[tid] * rsqrtf(var + 1e-5f);
        s_sc[tid] = sv;
        s_sh[tid] = beta[tid] - sv * mu;
    }
    const float4* Wg = (const float4*)W;
    float4* Ws4 = (float4*)Ws;
#pragma unroll
    for (int i = 0; i < 16; i++) Ws4[tid + 256 * i] = __ldg(Wg + tid + 256 * i);
    __syncthreads();

    for (int tile = blockIdx.x; tile < nTiles; tile += gridDim.x) {
        int row0 = tile * 64;
        for (int i = tid; i < 64 * 32; i += 256) {
            int r = i >> 5, c4 = i & 31;
            int gr = row0 + r;
            float4 v = make_float4(0.f, 0.f, 0.f, 0.f);
            if (gr < M) {
                float4 zv = __ldg((const float4*)(A + (size_t)gr * HID) + c4);
                float4 s4 = *(const float4*)&s_sc[c4 * 4];
                float4 h4 = *(const float4*)&s_sh[c4 * 4];
                v.x = fmaxf(fmaf(s4.x, zv.x, h4.x), 0.f);
                v.y = fmaxf(fmaf(s4.y, zv.y, h4.y), 0.f);
                v.z = fmaxf(fmaf(s4.z, zv.z, h4.z), 0.f);
                v.w = fmaxf(fmaf(s4.w, zv.w, h4.w), 0.f);
            }
            *(float4*)&As[r * 132 + c4 * 4] = v;
        }
        __syncthreads();
        gemm_tile_body<true, STATS>(Ws, As, bias, out, stat_out, row0, M, lane, wid);
    }
}

// ================= launcher =================
extern "C" void kernel_launch(void* const* d_in, const int* in_sizes, int n_in,
                              void* d_out, int out_size) {
    const float* x = (const float*)d_in[0];
    const int* ei = (const int*)d_in[1];
    const float* ea = (const float*)d_in[2];
    const float* W1 = (const float*)d_in[3];
    const float* b1 = (const float*)d_in[4];
    const float* g1 = (const float*)d_in[5];
    const float* be1 = (const float*)d_in[6];
    const float* W2 = (const float*)d_in[7];
    const float* b2 = (const float*)d_in[8];
    const float* bn_g = (const float*)d_in[9];
    const float* bn_b = (const float*)d_in[10];

    int M = in_sizes[0] / HID;
    int E = in_sizes[2] / HID;
    float* out = (float*)d_out;

    void *z_p, *t_p, *cnt_p, *stats_p;
    cudaGetSymbolAddress(&z_p, g_z);
    cudaGetSymbolAddress(&t_p, g_t);
    cudaGetSymbolAddress(&cnt_p, g_cnt);
    cudaGetSymbolAddress(&stats_p, g_stats);
    float* stats = (float*)stats_p;

    cudaFuncSetAttribute(k1_kernel<false>, cudaFuncAttributeMaxDynamicSharedMemorySize, GEMM_SMEM);
    cudaFuncSetAttribute(k1_kernel<true>, cudaFuncAttributeMaxDynamicSharedMemorySize, GEMM_SMEM);
    cudaFuncSetAttribute(k2_kernel<true>, cudaFuncAttributeMaxDynamicSharedMemorySize, GEMM_SMEM);
    cudaFuncSetAttribute(k2_kernel<false>, cudaFuncAttributeMaxDynamicSharedMemorySize, GEMM_SMEM);

    const int* srcI = ei;
    const int* dstI = ei + E;
    int eb = (E + 255) / 256;
    int nTiles = (M + 63) / 64;
    int pgrid = 304;  // 2 CTAs x 152 SMs
    float invN = 1.0f / (float)M;

    // ---- CSR build + stat zeroing ----
    cudaMemsetAsync(cnt_p, 0, (size_t)M * sizeof(int));
    cudaMemsetAsync(stats_p, 0, 8 * 2 * HID * sizeof(float));
    hist_kernel<<<eb, 256>>>(dstI, E);
    scan_kernel<<<1, 1024>>>(M, E);
    scatter_kernel<<<eb, 256>>>(dstI, E);

    for (int i = 0; i < 4; i++) {
        const float* zsrc = (i == 0) ? x : (const float*)z_p;
        float* stat_t = stats + (size_t)(2 * i) * 2 * HID;
        float* stat_z = stats + (size_t)(2 * i + 1) * 2 * HID;
        float* stat_z_prev = stats + (size_t)(2 * i - 1) * 2 * HID;

        if (i == 0)
            k1_kernel<false><<<pgrid, 256, GEMM_SMEM>>>(
                zsrc, ea, srcI, nullptr, nullptr, nullptr, invN,
                W1, b1, (float*)t_p, stat_t, M, nTiles);
        else
            k1_kernel<true><<<pgrid, 256, GEMM_SMEM>>>(
                zsrc, ea, srcI, stat_z_prev,
                bn_g + (size_t)(i - 1) * HID, bn_b + (size_t)(i - 1) * HID, invN,
                W1 + (size_t)i * HID * HID, b1 + (size_t)i * HID,
                (float*)t_p, stat_t, M, nTiles);

        if (i < 3)
            k2_kernel<true><<<pgrid, 256, GEMM_SMEM>>>(
                (const float*)t_p, stat_t,
                g1 + (size_t)i * HID, be1 + (size_t)i * HID, invN,
                W2 + (size_t)i * HID * HID, b2 + (size_t)i * HID,
                (float*)z_p, stat_z, M, nTiles);
        else
            k2_kernel<false><<<pgrid, 256, GEMM_SMEM>>>(
                (const float*)t_p, stat_t,
                g1 + (size_t)i * HID, be1 + (size_t)i * HID, invN,
                W2 + (size_t)i * HID * HID, b2 + (size_t)i * HID,
                out, nullptr, M, nTiles);
    }
}

// round 6
// speedup vs baseline: 1.4093x; 1.4093x over previous
#include <cuda_runtime.h>
#include <cuda_fp16.h>
#include <cstdint>

#define HID 128
#define MAXN 50000
#define MAXE 640000

// ---------------- scratch (device globals; no allocation allowed) ----------------
__device__ __align__(256) float g_z[MAXN * HID];        // raw (pre-BN) layer output
__device__ __align__(256) float g_agg[MAXN * HID];      // aggregation output
__device__ __align__(256) float g_t[MAXN * HID];        // post-GEMM1 pre-BN
__device__ __align__(256) float g_stats[8 * 2 * HID];   // per-layer [sum|sumsq] slots
__device__ __align__(256) __half g_eah[(size_t)MAXE * HID];  // fp16 edge_attr
__device__ int g_cnt[MAXN];       // histogram (re-zeroed by scan each call)
__device__ int g_cur[MAXN];       // scatter cursor (zeroed by scan each call)
__device__ int g_rowptr[MAXN + 1];
__device__ int g_elist[MAXE];

// ---------------- f32x2 helpers ----------------
__device__ __forceinline__ unsigned long long pk2(float a) {
    unsigned long long r;
    asm("mov.b64 %0, {%1, %1};" : "=l"(r) : "f"(a));
    return r;
}
__device__ __forceinline__ void fma2(unsigned long long& d, unsigned long long a, unsigned long long b) {
    asm("fma.rn.f32x2 %0, %1, %2, %0;" : "+l"(d) : "l"(a), "l"(b));
}
__device__ __forceinline__ float2 upk(unsigned long long v) {
    float2 r;
    asm("mov.b64 {%0, %1}, %2;" : "=f"(r.x), "=f"(r.y) : "l"(v));
    return r;
}

// ================= edge_attr fp32 -> fp16 (once) =================
__global__ void convert_kernel(const float* __restrict__ ea, int total16) {
    int i = blockIdx.x * blockDim.x + threadIdx.x;  // one 16B output chunk = 8 elems
    if (i >= total16) return;
    const float4* p = (const float4*)ea + (size_t)i * 2;
    float4 a = __ldcs(p);
    float4 b = __ldcs(p + 1);
    __half2 h0 = __floats2half2_rn(a.x, a.y);
    __half2 h1 = __floats2half2_rn(a.z, a.w);
    __half2 h2 = __floats2half2_rn(b.x, b.y);
    __half2 h3 = __floats2half2_rn(b.z, b.w);
    uint4 o;
    o.x = *(unsigned*)&h0; o.y = *(unsigned*)&h1;
    o.z = *(unsigned*)&h2; o.w = *(unsigned*)&h3;
    ((uint4*)g_eah)[i] = o;
}

// ================= CSR build =================
__global__ void hist_kernel(const int* __restrict__ dst, int E) {
    int i = blockIdx.x * blockDim.x + threadIdx.x;
    if (i < E) atomicAdd(&g_cnt[dst[i]], 1);
}

// scan + zero cnt/cur/stats (keeps replays deterministic without extra memsets)
__global__ void __launch_bounds__(1024) scan_kernel(int N, int E) {
    __shared__ int part[1024];
    int tid = threadIdx.x;
    int chunk = (N + 1023) / 1024;
    int base = tid * chunk;
    int s = 0;
    for (int j = 0; j < chunk; j++) {
        int idx = base + j;
        if (idx < N) s += g_cnt[idx];
    }
    part[tid] = s;
    __syncthreads();
    for (int off = 1; off < 1024; off <<= 1) {
        int v = (tid >= off) ? part[tid - off] : 0;
        __syncthreads();
        part[tid] += v;
        __syncthreads();
    }
    int run = (tid == 0) ? 0 : part[tid - 1];
    for (int j = 0; j < chunk; j++) {
        int idx = base + j;
        if (idx < N) {
            g_rowptr[idx] = run;
            run += g_cnt[idx];
            g_cnt[idx] = 0;
            g_cur[idx] = 0;
        }
    }
    if (tid == 1023) g_rowptr[N] = E;
    // zero the 8 stat slots (2048 floats)
    g_stats[tid] = 0.f;
    g_stats[tid + 1024] = 0.f;
}

__global__ void scatter_kernel(const int* __restrict__ dst, int E) {
    int i = blockIdx.x * blockDim.x + threadIdx.x;
    if (i < E) {
        int d = dst[i];
        int p = atomicAdd(&g_cur[d], 1);
        g_elist[g_rowptr[d] + p] = i;
    }
}

// ================= aggregate: warp per node, no atomics, fp16 edge_attr ============
template <bool BN>
__global__ void __launch_bounds__(256) agg_kernel(
    const float* __restrict__ z, const int* __restrict__ srcI,
    const float* __restrict__ stat_in,
    const float* __restrict__ gamma, const float* __restrict__ beta,
    float* __restrict__ agg, int N, float invN) {
    __shared__ float s_sc[HID], s_sh[HID];
    if (BN) {
        if (threadIdx.x < HID) {
            int c = threadIdx.x;
            float mu = stat_in[c] * invN;
            float var = stat_in[HID + c] * invN - mu * mu;
            float sv = gamma[c] * rsqrtf(var + 1e-5f);
            s_sc[c] = sv;
            s_sh[c] = beta[c] - sv * mu;
        }
        __syncthreads();
    }
    int warp = (blockIdx.x * blockDim.x + threadIdx.x) >> 5;
    int lane = threadIdx.x & 31;
    if (warp >= N) return;

    float4 sc, sh;
    if (BN) {
        sc = *(const float4*)&s_sc[lane * 4];
        sh = *(const float4*)&s_sh[lane * 4];
    }

    int idx = g_rowptr[warp];
    const int end = g_rowptr[warp + 1];
    float4 acc = make_float4(0.f, 0.f, 0.f, 0.f);

#define EDGE_BODY(E_, S_)                                                       \
    {                                                                           \
        float4 zv = __ldg((const float4*)(z + (size_t)(S_) * HID) + lane);      \
        uint2 raw = __ldcs((const uint2*)(g_eah + (size_t)(E_) * HID) + lane);  \
        float2 f0 = __half22float2(*(__half2*)&raw.x);                          \
        float2 f1 = __half22float2(*(__half2*)&raw.y);                          \
        if (BN) {                                                               \
            zv.x = fmaf(sc.x, zv.x, sh.x); zv.y = fmaf(sc.y, zv.y, sh.y);       \
            zv.z = fmaf(sc.z, zv.z, sh.z); zv.w = fmaf(sc.w, zv.w, sh.w);       \
        }                                                                       \
        acc.x += fmaxf(zv.x + f0.x, 0.f);                                       \
        acc.y += fmaxf(zv.y + f0.y, 0.f);                                       \
        acc.z += fmaxf(zv.z + f1.x, 0.f);                                       \
        acc.w += fmaxf(zv.w + f1.y, 0.f);                                       \
    }

    for (; idx + 4 <= end; idx += 4) {
        int e0 = __ldg(g_elist + idx);
        int e1 = __ldg(g_elist + idx + 1);
        int e2 = __ldg(g_elist + idx + 2);
        int e3 = __ldg(g_elist + idx + 3);
        int s0 = __ldg(srcI + e0);
        int s1 = __ldg(srcI + e1);
        int s2 = __ldg(srcI + e2);
        int s3 = __ldg(srcI + e3);
        EDGE_BODY(e0, s0) EDGE_BODY(e1, s1) EDGE_BODY(e2, s2) EDGE_BODY(e3, s3)
    }
    for (; idx < end; idx++) {
        int e0 = __ldg(g_elist + idx);
        int s0 = __ldg(srcI + e0);
        EDGE_BODY(e0, s0)
    }
#undef EDGE_BODY
    ((float4*)(agg + (size_t)warp * HID))[lane] = acc;  // every row written: no memset
}

// ================= fused GEMM (R4 mapping: warp w rows w*8, lane cols lane*4) ======
static const int GEMM_SMEM = (HID * HID + 64 * 132 + 2 * HID) * 4;  // 100352 B

template <bool BN_IN, bool HAS_A2, bool RELU_IN, bool RELU_OUT, bool STATS>
__global__ void __launch_bounds__(256) gemm_kernel(
    const float* __restrict__ A, const float* __restrict__ A2,
    const float* __restrict__ stat_in, const float* __restrict__ gamma,
    const float* __restrict__ beta, float invN,
    const float* __restrict__ W, const float* __restrict__ bias,
    float* __restrict__ out, float* __restrict__ stat_out, int M) {
    extern __shared__ float smem[];
    float* Ws = smem;                        // [128][128]
    float* As = smem + HID * HID;            // [64][132]
    float* s_sc = smem + HID * HID + 64 * 132;
    float* s_sh = s_sc + HID;

    const int tid = threadIdx.x;
    const int lane = tid & 31;
    const int wid = tid >> 5;
    const int row0 = blockIdx.x * 64;

    if (tid < HID) {
        if (BN_IN) {
            float mu = stat_in[tid] * invN;
            float var = stat_in[HID + tid] * invN - mu * mu;
            float sv = gamma[tid] * rsqrtf(var + 1e-5f);
            s_sc[tid] = sv;
            s_sh[tid] = beta[tid] - sv * mu;
        } else {
            s_sc[tid] = 1.f;
            s_sh[tid] = 0.f;
        }
    }

    const float4* Wg = (const float4*)W;
    float4* Ws4 = (float4*)Ws;
#pragma unroll
    for (int i = 0; i < 16; i++) Ws4[tid + 256 * i] = __ldg(Wg + tid + 256 * i);
    __syncthreads();

    for (int i = tid; i < 64 * 32; i += 256) {
        int r = i >> 5, c4 = i & 31;
        int gr = row0 + r;
        float4 v = make_float4(0.f, 0.f, 0.f, 0.f);
        if (gr < M) {
            float4 zv = __ldg((const float4*)(A + (size_t)gr * HID) + c4);
            float4 s4 = *(const float4*)&s_sc[c4 * 4];
            float4 h4 = *(const float4*)&s_sh[c4 * 4];
            v.x = fmaf(s4.x, zv.x, h4.x);
            v.y = fmaf(s4.y, zv.y, h4.y);
            v.z = fmaf(s4.z, zv.z, h4.z);
            v.w = fmaf(s4.w, zv.w, h4.w);
            if (RELU_IN) {
                v.x = fmaxf(v.x, 0.f); v.y = fmaxf(v.y, 0.f);
                v.z = fmaxf(v.z, 0.f); v.w = fmaxf(v.w, 0.f);
            }
            if (HAS_A2) {
                float4 g4 = __ldg((const float4*)(A2 + (size_t)gr * HID) + c4);
                v.x += g4.x; v.y += g4.y; v.z += g4.z; v.w += g4.w;
            }
        }
        *(float4*)&As[r * 132 + c4 * 4] = v;
    }
    __syncthreads();

    unsigned long long acc[16];
#pragma unroll
    for (int i = 0; i < 16; i++) acc[i] = 0ull;

    const int arow = wid * 8;
#pragma unroll 2
    for (int kk = 0; kk < HID; kk += 4) {
        float ar[8][4];
#pragma unroll
        for (int r = 0; r < 8; r++)
            *(float4*)ar[r] = *(const float4*)&As[(arow + r) * 132 + kk];
#pragma unroll
        for (int j = 0; j < 4; j++) {
            ulonglong2 w = *(const ulonglong2*)&Ws[(kk + j) * HID + lane * 4];
#pragma unroll
            for (int r = 0; r < 8; r++) {
                unsigned long long pa = pk2(ar[r][j]);
                fma2(acc[r * 2 + 0], pa, w.x);
                fma2(acc[r * 2 + 1], pa, w.y);
            }
        }
    }

    float bb[4];
    *(float4*)bb = __ldg((const float4*)bias + lane);
    float csum[4], csq[4];
#pragma unroll
    for (int j = 0; j < 4; j++) { csum[j] = 0.f; csq[j] = 0.f; }

#pragma unroll
    for (int r = 0; r < 8; r++) {
        int gr = row0 + arow + r;
        if (gr < M) {
            float2 u0 = upk(acc[r * 2 + 0]);
            float2 u1 = upk(acc[r * 2 + 1]);
            float v[4] = {u0.x + bb[0], u0.y + bb[1], u1.x + bb[2], u1.y + bb[3]};
            if (RELU_OUT) {
#pragma unroll
                for (int j = 0; j < 4; j++) v[j] = fmaxf(v[j], 0.f);
            }
            *(float4*)(out + (size_t)gr * HID + lane * 4) = make_float4(v[0], v[1], v[2], v[3]);
            if (STATS) {
#pragma unroll
                for (int j = 0; j < 4; j++) { csum[j] += v[j]; csq[j] += v[j] * v[j]; }
            }
        }
    }

    if (STATS) {
        float* red = As;  // reuse: 8 warps x 256 floats
        __syncthreads();
#pragma unroll
        for (int j = 0; j < 4; j++) {
            red[wid * 256 + lane * 4 + j] = csum[j];
            red[wid * 256 + 128 + lane * 4 + j] = csq[j];
        }
        __syncthreads();
#pragma unroll
        for (int s = 4; s > 0; s >>= 1) {
            if (wid < s) {
                for (int i = lane; i < 256; i += 32)
                    red[wid * 256 + i] += red[(wid + s) * 256 + i];
            }
            __syncthreads();
        }
        if (wid == 0) {
#pragma unroll
            for (int j = 0; j < 4; j++) {
                atomicAdd(&stat_out[lane * 4 + j], red[lane * 4 + j]);
                atomicAdd(&stat_out[HID + lane * 4 + j], red[128 + lane * 4 + j]);
            }
        }
    }
}

// ================= launcher =================
extern "C" void kernel_launch(void* const* d_in, const int* in_sizes, int n_in,
                              void* d_out, int out_size) {
    const float* x = (const float*)d_in[0];
    const int* ei = (const int*)d_in[1];   // int32 (JAX default, x64 disabled)
    const float* ea = (const float*)d_in[2];
    const float* W1 = (const float*)d_in[3];
    const float* b1 = (const float*)d_in[4];
    const float* g1 = (const float*)d_in[5];
    const float* be1 = (const float*)d_in[6];
    const float* W2 = (const float*)d_in[7];
    const float* b2 = (const float*)d_in[8];
    const float* bn_g = (const float*)d_in[9];
    const float* bn_b = (const float*)d_in[10];

    int M = in_sizes[0] / HID;
    int E = in_sizes[2] / HID;
    float* out = (float*)d_out;

    void *agg_p, *z_p, *t_p, *stats_p;
    cudaGetSymbolAddress(&agg_p, g_agg);
    cudaGetSymbolAddress(&z_p, g_z);
    cudaGetSymbolAddress(&t_p, g_t);
    cudaGetSymbolAddress(&stats_p, g_stats);
    float* stats = (float*)stats_p;

    cudaFuncSetAttribute(gemm_kernel<false, true, false, false, true>,
                         cudaFuncAttributeMaxDynamicSharedMemorySize, GEMM_SMEM);
    cudaFuncSetAttribute(gemm_kernel<true, true, false, false, true>,
                         cudaFuncAttributeMaxDynamicSharedMemorySize, GEMM_SMEM);
    cudaFuncSetAttribute(gemm_kernel<true, false, true, true, true>,
                         cudaFuncAttributeMaxDynamicSharedMemorySize, GEMM_SMEM);
    cudaFuncSetAttribute(gemm_kernel<true, false, true, true, false>,
                         cudaFuncAttributeMaxDynamicSharedMemorySize, GEMM_SMEM);

    const int* srcI = ei;
    const int* dstI = ei + E;
    int eb = (E + 255) / 256;
    int gb = (M + 63) / 64;
    int ab = (M * 32 + 255) / 256;  // warp per node
    int total16 = E * (HID / 8);    // 16B chunks in ea
    int cb = (total16 + 255) / 256;
    float invN = 1.0f / (float)M;

    // launches 1-4: convert + CSR (scan also zeroes stats/cnt/cur for replays)
    convert_kernel<<<cb, 256>>>(ea, total16);
    hist_kernel<<<eb, 256>>>(dstI, E);
    scan_kernel<<<1, 1024>>>(M, E);
    scatter_kernel<<<eb, 256>>>(dstI, E);

    for (int i = 0; i < 4; i++) {
        const float* zsrc = (i == 0) ? x : (const float*)z_p;
        float* stat_t = stats + (size_t)(2 * i) * 2 * HID;
        float* stat_z = stats + (size_t)(2 * i + 1) * 2 * HID;
        float* stat_z_prev = stats + (size_t)(2 * i - 1) * 2 * HID;

        if (i == 0)
            agg_kernel<false><<<ab, 256>>>(zsrc, srcI, nullptr, nullptr, nullptr,
                                           (float*)agg_p, M, invN);
        else
            agg_kernel<true><<<ab, 256>>>(zsrc, srcI, stat_z_prev,
                                          bn_g + (size_t)(i - 1) * HID,
                                          bn_b + (size_t)(i - 1) * HID,
                                          (float*)agg_p, M, invN);

        if (i == 0)
            gemm_kernel<false, true, false, false, true><<<gb, 256, GEMM_SMEM>>>(
                zsrc, (const float*)agg_p, nullptr, nullptr, nullptr, invN,
                W1, b1, (float*)t_p, stat_t, M);
        else
            gemm_kernel<true, true, false, false, true><<<gb, 256, GEMM_SMEM>>>(
                zsrc, (const float*)agg_p, stat_z_prev,
                bn_g + (size_t)(i - 1) * HID, bn_b + (size_t)(i - 1) * HID, invN,
                W1 + (size_t)i * HID * HID, b1 + (size_t)i * HID,
                (float*)t_p, stat_t, M);

        if (i < 3)
            gemm_kernel<true, false, true, true, true><<<gb, 256, GEMM_SMEM>>>(
                (const float*)t_p, nullptr, stat_t,
                g1 + (size_t)i * HID, be1 + (size_t)i * HID, invN,
                W2 + (size_t)i * HID * HID, b2 + (size_t)i * HID,
                (float*)z_p, stat_z, M);
        else
            gemm_kernel<true, false, true, true, false><<<gb, 256, GEMM_SMEM>>>(
                (const float*)t_p, nullptr, stat_t,
                g1 + (size_t)i * HID, be1 + (size_t)i * HID, invN,
                W2 + (size_t)i * HID * HID, b2 + (size_t)i * HID,
                out, nullptr, M);
    }
}